// round 4
// baseline (speedup 1.0000x reference)
#include <cuda_runtime.h>
#include <cuda_bf16.h>

#define FULL 0xffffffffu

static constexpr int B   = 256;
static constexpr int D   = 128;
static constexpr int K   = 8192;
static constexpr int KP1 = K + 1;
static constexpr int ENT = B * KP1;                  // 2,097,408
static constexpr int NROWS = 500000;
static constexpr int BROWS = 160;                    // rows per bucket
static constexpr int NBUCK = NROWS / BROWS;          // 3125 (exact)
static constexpr long long BANK  = (long long)NROWS * D;   // 64,000,000 floats
static constexpr long long BANK4 = BANK / 4;

__device__ int      g_cnt[NBUCK];
__device__ int      g_off[NBUCK + 1];
__device__ int      g_cur[NBUCK];
__device__ unsigned g_ent[ENT];        // rloc | b<<8 | pos<<16
__device__ float    g_sc0[ENT];        // view0 exp-scores, sign-flagged (neg = positive sample)
__device__ float    g_sc1[ENT];        // view1 exp-scores, sign-flagged
__device__ uint2    g_fsb[B * 32];     // f_s as bf16, 4 dims per uint2
__device__ uint2    g_ftb[B * 32];     // f_t as bf16
__device__ double   g_sum[2];
__device__ double   g_loss;
__device__ int      g_winner[B];

__device__ __forceinline__ float kINV_T() { return (float)(1.0 / 0.07); }
__device__ __forceinline__ float kMPN()   { return (float)(8192.0 / 500000.0); }
__device__ __forceinline__ float kDENOM() { return (float)(8192.0 / 500000.0 + 1e-7); }

__device__ __forceinline__ uint2 pack4(float4 v) {
    uint2 r;
    asm("cvt.rn.bf16x2.f32 %0, %1, %2;" : "=r"(r.x) : "f"(v.y), "f"(v.x));
    asm("cvt.rn.bf16x2.f32 %0, %1, %2;" : "=r"(r.y) : "f"(v.w), "f"(v.z));
    return r;
}

// dot of 4 bf16 dims (packed uint2) against 4 bf16 dims, fp32 accumulate
__device__ __forceinline__ float dotbf(uint2 a, uint2 f) {
    float ax = __uint_as_float(a.x << 16);
    float ay = __uint_as_float(a.x & 0xffff0000u);
    float az = __uint_as_float(a.y << 16);
    float aw = __uint_as_float(a.y & 0xffff0000u);
    float fx = __uint_as_float(f.x << 16);
    float fy = __uint_as_float(f.x & 0xffff0000u);
    float fz = __uint_as_float(f.y << 16);
    float fw = __uint_as_float(f.y & 0xffff0000u);
    return ax * fx + ay * fy + az * fz + aw * fw;
}

// --- init: zero counters/sums, winners, copy edge scalars, f -> bf16 convert
__global__ void k_zero(const int* __restrict__ idx,
                       const float* __restrict__ f_s, const float* __restrict__ f_t,
                       const float* __restrict__ mv1, const float* __restrict__ mv2,
                       float* __restrict__ out) {
    int t = blockIdx.x * 256 + threadIdx.x;   // 4096 threads
    if (t < NBUCK) g_cnt[t] = 0;
    if (t < 2) g_sum[t] = 0.0;
    if (t == 2) g_loss = 0.0;
    if (t == 3) {
        out[1] = mv1[0]; out[2] = mv1[1]; out[3] = mv1[2];
        out[BANK] = mv1[BANK - 1];
        out[1 + BANK] = mv2[0]; out[2 + BANK] = mv2[1]; out[3 + BANK] = mv2[2];
        out[2 * BANK] = mv2[BANK - 1];
    }
    if (t < B) {
        int my = idx[t];
        int win = 1;
        for (int b2 = t + 1; b2 < B; b2++)
            if (idx[b2] == my) win = 0;
        g_winner[t] = win;
    }
    // convert f_s/f_t to bf16: 8192 uint2 each, 2 per thread
    const float4* fs4 = (const float4*)f_s;
    const float4* ft4 = (const float4*)f_t;
    #pragma unroll
    for (int u = 0; u < 2; u++) {
        int i = t * 2 + u;                    // < 8192
        g_fsb[i] = pack4(fs4[i]);
        g_ftb[i] = pack4(ft4[i]);
    }
}

// --- histogram by row bucket (int4 loads, 4 atomics in flight)
__global__ void __launch_bounds__(256) k_hist(const int* __restrict__ idx,
                                              const int* __restrict__ cidx) {
    int t = blockIdx.x * 256 + threadIdx.x;   // 524288 threads, one int4 each
    int4 v = ((const int4*)cidx)[t];
    atomicAdd(&g_cnt[v.x / BROWS], 1);
    atomicAdd(&g_cnt[v.y / BROWS], 1);
    atomicAdd(&g_cnt[v.z / BROWS], 1);
    atomicAdd(&g_cnt[v.w / BROWS], 1);
    if (t < B) atomicAdd(&g_cnt[idx[t] / BROWS], 1);
}

// --- exclusive scan over 3125 bucket counts (single block)
__global__ void k_scan() {
    __shared__ int sh[1024];
    int t = threadIdx.x;
    int base = t * 4;
    int loc[4];
    int s = 0;
    #pragma unroll
    for (int i = 0; i < 4; i++) {
        int v = (base + i < NBUCK) ? g_cnt[base + i] : 0;
        loc[i] = s;
        s += v;
    }
    sh[t] = s;
    __syncthreads();
    for (int off = 1; off < 1024; off <<= 1) {
        int v = (t >= off) ? sh[t - off] : 0;
        __syncthreads();
        sh[t] += v;
        __syncthreads();
    }
    int pre = (t > 0) ? sh[t - 1] : 0;
    #pragma unroll
    for (int i = 0; i < 4; i++) {
        if (base + i < NBUCK) {
            int o = pre + loc[i];
            g_off[base + i] = o;
            g_cur[base + i] = o;
        }
    }
    if (t == 1023) g_off[NBUCK] = sh[1023];
}

// --- scatter references into bucket order
__global__ void __launch_bounds__(256) k_scatter(const int* __restrict__ idx,
                                                 const int* __restrict__ cidx) {
    int t = blockIdx.x * 256 + threadIdx.x;
    int4 v = ((const int4*)cidx)[t];
    unsigned b = (unsigned)(t >> 11);         // 4t >> 13
    int rows[4] = {v.x, v.y, v.z, v.w};
    #pragma unroll
    for (int u = 0; u < 4; u++) {
        int row = rows[u];
        int bu = row / BROWS;
        int rloc = row - bu * BROWS;
        int pos = atomicAdd(&g_cur[bu], 1);
        g_ent[pos] = (unsigned)rloc | (b << 8);
    }
    if (t < B) {
        int row = idx[t];
        int bu = row / BROWS;
        int rloc = row - bu * BROWS;
        int pos = atomicAdd(&g_cur[bu], 1);
        g_ent[pos] = (unsigned)rloc | ((unsigned)t << 8) | (1u << 16);
    }
}

// --- main: per bucket — stage rows (bf16) + fused copy; stage f (bf16); score
__global__ void __launch_bounds__(256) k_main(
        const float* __restrict__ mv1, const float* __restrict__ mv2,
        float* __restrict__ out) {
    extern __shared__ uint2 sm[];
    // layout (uint2): smA rows mv1 [0,5120), smB rows mv2 [5120,10240),
    //                 smFs [10240,18432), smFt [18432,26624)
    uint2* smA  = sm;
    uint2* smB  = sm + 5120;
    uint2* smFs = sm + 10240;
    uint2* smFt = sm + 18432;
    __shared__ double shs[16];

    int beta = blockIdx.x;
    int lane = threadIdx.x & 31;
    int wrp  = threadIdx.x >> 5;
    long long s4 = (long long)beta * (BROWS * 32);   // first float4 of bucket

    const float4* b14 = (const float4*)mv1;
    const float4* b24 = (const float4*)mv2;
    float4* out4 = (float4*)out;

    // phase 1a: stream bucket rows (both banks), convert to smem bf16, fused copy
    #pragma unroll 4
    for (int j = threadIdx.x; j < BROWS * 32; j += 256) {
        long long m = s4 + j;
        float4 c1 = __ldcs(&b14[m]);
        float4 c2 = __ldcs(&b24[m]);
        smA[j] = pack4(c1);
        smB[j] = pack4(c2);
        float p1 = __shfl_up_sync(FULL, c1.w, 1);
        float p2 = __shfl_up_sync(FULL, c2.w, 1);
        if (lane == 0 && m > 0) {
            p1 = __ldcs(&mv1[4 * m - 1]);
            p2 = __ldcs(&mv2[4 * m - 1]);
        }
        if (m != 0) {
            __stcs(&out4[m],         make_float4(p1, c1.x, c1.y, c1.z));
            __stcs(&out4[BANK4 + m], make_float4(p2, c2.x, c2.y, c2.z));
        }
    }
    // phase 1b: stage all f_s/f_t bf16 (128 KB) via uint4
    {
        const uint4* gfs = (const uint4*)g_fsb;
        const uint4* gft = (const uint4*)g_ftb;
        uint4* sfs = (uint4*)smFs;
        uint4* sft = (uint4*)smFt;
        #pragma unroll 4
        for (int j = threadIdx.x; j < 4096; j += 256) {
            sfs[j] = gfs[j];
            sft[j] = gft[j];
        }
    }
    __syncthreads();

    // phase 2: score this bucket's entries from smem
    int base = g_off[beta];
    int end  = g_off[beta + 1];
    double acc0 = 0.0, acc1 = 0.0;

    for (int e0 = base + wrp * 8; e0 < end; e0 += 64) {
        int cnt = min(8, end - e0);
        unsigned ent = 0;
        if (lane < cnt) ent = g_ent[e0 + lane];

        float d0[8], d1[8];
        #pragma unroll
        for (int j = 0; j < 8; j++) {
            unsigned ej = __shfl_sync(FULL, ent, j);
            int rloc = (int)(ej & 255u);
            int b    = (int)((ej >> 8) & 255u);
            uint2 a1 = smA[rloc * 32 + lane];
            uint2 a2 = smB[rloc * 32 + lane];
            uint2 fs = smFs[b * 32 + lane];
            uint2 ft = smFt[b * 32 + lane];
            d0[j] = dotbf(a2, fs);     // view0: <mv2_row, f_s>
            d1[j] = dotbf(a1, ft);     // view1: <mv1_row, f_t>
        }
        #pragma unroll
        for (int off = 16; off > 0; off >>= 1) {
            #pragma unroll
            for (int j = 0; j < 8; j++) {
                d0[j] += __shfl_xor_sync(FULL, d0[j], off);
                d1[j] += __shfl_xor_sync(FULL, d1[j], off);
            }
        }
        #pragma unroll
        for (int j = 0; j < 8; j++) {
            if (lane == j && j < cnt) {
                float w0 = expf(d0[j] * kINV_T());
                float w1 = expf(d1[j] * kINV_T());
                bool pos = (ent >> 16) != 0;
                g_sc0[e0 + j] = pos ? -w0 : w0;
                g_sc1[e0 + j] = pos ? -w1 : w1;
                acc0 += (double)w0;
                acc1 += (double)w1;
            }
        }
    }

    #pragma unroll
    for (int off = 16; off > 0; off >>= 1) {
        acc0 += __shfl_xor_sync(FULL, acc0, off);
        acc1 += __shfl_xor_sync(FULL, acc1, off);
    }
    if (lane == 0) { shs[wrp] = acc0; shs[8 + wrp] = acc1; }
    __syncthreads();
    if (threadIdx.x == 0) {
        double s0 = 0.0, s1 = 0.0;
        #pragma unroll
        for (int j = 0; j < 8; j++) { s0 += shs[j]; s1 += shs[8 + j]; }
        atomicAdd(&g_sum[0], s0);
        atomicAdd(&g_sum[1], s1);
    }
}

// --- loss reduction over linear score arrays
__global__ void __launch_bounds__(256) k2_loss() {
    double Z0 = g_sum[0] * (500000.0 / 2097408.0);
    double Z1 = g_sum[1] * (500000.0 / 2097408.0);
    float Zf0 = (float)Z0, Zf1 = (float)Z1;

    const int NT = 512 * 256;
    int tid = blockIdx.x * 256 + threadIdx.x;
    double acc = 0.0;

    #pragma unroll 4
    for (int i = tid; i < 2 * ENT; i += NT) {
        int v1 = (i >= ENT);
        float s = v1 ? g_sc1[i - ENT] : g_sc0[i];
        float Zf = v1 ? Zf1 : Zf0;
        float y = fabsf(s) / Zf;
        float t = (s < 0.0f) ? logf(y / (y + kDENOM()))
                             : logf(kMPN() / (y + kDENOM()));
        acc += (double)t;
    }

    #pragma unroll
    for (int off = 16; off > 0; off >>= 1)
        acc += __shfl_xor_sync(FULL, acc, off);
    __shared__ double sh[8];
    int lane = threadIdx.x & 31, wid = threadIdx.x >> 5;
    if (lane == 0) sh[wid] = acc;
    __syncthreads();
    if (threadIdx.x == 0) {
        double s = 0.0;
        for (int j = 0; j < 8; j++) s += sh[j];
        atomicAdd(&g_loss, s);
    }
}

// --- momentum scatter update of the 256 touched rows
__global__ void k3_update(const float* __restrict__ f_s, const float* __restrict__ f_t,
                          const float* __restrict__ mv1, const float* __restrict__ mv2,
                          const int* __restrict__ idx, float* __restrict__ out) {
    int u = blockIdx.x;       // 512 blocks
    int v = u >> 8;
    int b = u & 255;
    if (!g_winner[b]) return;
    int row = idx[b];
    const float* mem = v ? mv2 : mv1;
    const float* f   = v ? f_t : f_s;
    float* dst = out + 1 + (size_t)v * BANK + (size_t)row * D;
    int t = threadIdx.x;      // 128 threads
    float nv = mem[(long long)row * D + t] * 0.5f + f[b * D + t] * 0.5f;
    float s = nv * nv;
    #pragma unroll
    for (int off = 16; off > 0; off >>= 1)
        s += __shfl_xor_sync(FULL, s, off);
    __shared__ float sh[4];
    if ((t & 31) == 0) sh[t >> 5] = s;
    __syncthreads();
    float tot = sh[0] + sh[1] + sh[2] + sh[3];
    dst[t] = nv / sqrtf(tot);
}

__global__ void k_final(float* __restrict__ out) {
    out[0] = (float)(-g_loss / 256.0);
}

extern "C" void kernel_launch(void* const* d_in, const int* in_sizes, int n_in,
                              void* d_out, int out_size) {
    const float* f_s  = (const float*)d_in[0];
    const float* f_t  = (const float*)d_in[1];
    const float* mv1  = (const float*)d_in[2];
    const float* mv2  = (const float*)d_in[3];
    const int*   idx  = (const int*)d_in[4];
    const int*   cidx = (const int*)d_in[5];
    float* out = (float*)d_out;

    static int smem_set = 0;
    if (!smem_set) {
        cudaFuncSetAttribute(k_main, cudaFuncAttributeMaxDynamicSharedMemorySize, 212992);
        smem_set = 1;
    }

    k_zero<<<16, 256>>>(idx, f_s, f_t, mv1, mv2, out);
    k_hist<<<2048, 256>>>(idx, cidx);
    k_scan<<<1, 1024>>>();
    k_scatter<<<2048, 256>>>(idx, cidx);
    k_main<<<NBUCK, 256, 212992>>>(mv1, mv2, out);
    k2_loss<<<512, 256>>>();
    k3_update<<<512, 128>>>(f_s, f_t, mv1, mv2, idx, out);
    k_final<<<1, 1>>>(out);
}

// round 5
// speedup vs baseline: 3.3910x; 3.3910x over previous
#include <cuda_runtime.h>
#include <cuda_bf16.h>

#define FULL 0xffffffffu

static constexpr int B   = 256;
static constexpr int D   = 128;
static constexpr int K   = 8192;
static constexpr int ENT = B * (K + 1);              // 2,097,408 (for Z mean)
static constexpr int NEG_TOT = 2 * B * K;
static constexpr long long BANK  = 500000LL * D;     // 64,000,000 floats
static constexpr long long BANK4 = BANK / 4;         // 16,000,000

__device__ uint2  g_b1h[BANK4];       // mv1 as bf16 (4 dims per uint2) - 128 MB
__device__ uint2  g_b2h[BANK4];       // mv2 as bf16                    - 128 MB
__device__ float  g_neg[NEG_TOT];     // [2][B][K] exp-scores, negatives
__device__ float  g_pos[2 * B];       // [2][B]    exp-scores, positives
__device__ uint2  g_fsb[B * 32];      // f_s bf16
__device__ uint2  g_ftb[B * 32];      // f_t bf16
__device__ double g_sum[2];
__device__ double g_loss;
__device__ int    g_winner[B];

__device__ __forceinline__ float kINV_T() { return (float)(1.0 / 0.07); }
__device__ __forceinline__ float kMPN()   { return (float)(8192.0 / 500000.0); }
__device__ __forceinline__ float kDENOM() { return (float)(8192.0 / 500000.0 + 1e-7); }

__device__ __forceinline__ uint2 pack4(float4 v) {
    uint2 r;
    asm("cvt.rn.bf16x2.f32 %0, %1, %2;" : "=r"(r.x) : "f"(v.y), "f"(v.x));
    asm("cvt.rn.bf16x2.f32 %0, %1, %2;" : "=r"(r.y) : "f"(v.w), "f"(v.z));
    return r;
}

__device__ __forceinline__ float dotbf(uint2 a, uint2 f) {
    float ax = __uint_as_float(a.x << 16);
    float ay = __uint_as_float(a.x & 0xffff0000u);
    float az = __uint_as_float(a.y << 16);
    float aw = __uint_as_float(a.y & 0xffff0000u);
    float fx = __uint_as_float(f.x << 16);
    float fy = __uint_as_float(f.x & 0xffff0000u);
    float fz = __uint_as_float(f.y << 16);
    float fw = __uint_as_float(f.y & 0xffff0000u);
    return ax * fx + ay * fy + az * fz + aw * fw;
}

// --- init: sums, winners, copy-edge scalars, f -> bf16
__global__ void k_zero(const int* __restrict__ idx,
                       const float* __restrict__ f_s, const float* __restrict__ f_t,
                       const float* __restrict__ mv1, const float* __restrict__ mv2,
                       float* __restrict__ out) {
    int t = blockIdx.x * 256 + threadIdx.x;   // 4096 threads
    if (t < 2) g_sum[t] = 0.0;
    if (t == 2) g_loss = 0.0;
    if (t == 3) {
        out[1] = mv1[0]; out[2] = mv1[1]; out[3] = mv1[2];
        out[BANK] = mv1[BANK - 1];
        out[1 + BANK] = mv2[0]; out[2 + BANK] = mv2[1]; out[3 + BANK] = mv2[2];
        out[2 * BANK] = mv2[BANK - 1];
    }
    if (t < B) {
        int my = idx[t];
        int win = 1;
        for (int b2 = t + 1; b2 < B; b2++)
            if (idx[b2] == my) win = 0;
        g_winner[t] = win;
    }
    const float4* fs4 = (const float4*)f_s;
    const float4* ft4 = (const float4*)f_t;
    #pragma unroll
    for (int u = 0; u < 2; u++) {
        int i = t * 2 + u;                    // < 8192
        g_fsb[i] = pack4(fs4[i]);
        g_ftb[i] = pack4(ft4[i]);
    }
}

// --- stream: bank copy into out (shifted float4) + bf16 replica, one pass
__global__ void __launch_bounds__(256) k_stream(
        const float* __restrict__ mv1, const float* __restrict__ mv2,
        float* __restrict__ out) {
    const float4* b14 = (const float4*)mv1;
    const float4* b24 = (const float4*)mv2;
    float4* out4 = (float4*)out;
    long long i0 = (long long)blockIdx.x * 256 + threadIdx.x;
    long long stride = (long long)gridDim.x * 256;
    for (long long m = i0; m < BANK4; m += stride) {
        float4 c1 = __ldcs(&b14[m]);
        float4 c2 = __ldcs(&b24[m]);
        g_b1h[m] = pack4(c1);
        g_b2h[m] = pack4(c2);
        if (m != 0) {
            float p1 = __ldcs(&mv1[4 * m - 1]);
            float p2 = __ldcs(&mv2[4 * m - 1]);
            __stcs(&out4[m],         make_float4(p1, c1.x, c1.y, c1.z));
            __stcs(&out4[BANK4 + m], make_float4(p2, c2.x, c2.y, c2.z));
        }
    }
}

// --- gather + score both views per chunk from bf16 replica
__global__ void __launch_bounds__(256) k_gather(
        const float* __restrict__ f_s, const float* __restrict__ f_t,
        const float* __restrict__ mv1, const float* __restrict__ mv2,
        const int* __restrict__ idx, const int* __restrict__ cidx) {
    int bid = blockIdx.x;
    int lane = threadIdx.x & 31;
    int wrp  = threadIdx.x >> 5;

    if (bid < 64) {
        // ---- positives (fp32 path): 512 warps, one (view, b) each
        int w = bid * 8 + wrp;
        int v = w >> 8;
        int b = w & 255;
        const float4* mem = (const float4*)(v ? mv1 : mv2);
        const float4* f   = (const float4*)(v ? f_t : f_s);
        int row = idx[b];
        float4 fv = f[b * 32 + lane];
        float4 wv = mem[(long long)row * 32 + lane];
        float d = wv.x * fv.x + wv.y * fv.y + wv.z * fv.z + wv.w * fv.w;
        #pragma unroll
        for (int off = 16; off > 0; off >>= 1)
            d += __shfl_xor_sync(FULL, d, off);
        if (lane == 0) {
            float e = expf(d * kINV_T());
            g_pos[w] = e;
            atomicAdd(&g_sum[v], (double)e);
        }
        return;
    }

    // ---- negatives: one warp per 8-k chunk, BOTH views
    int g = (bid - 64) * 8 + wrp;     // 0..262143
    int b = g >> 10;
    int c = g & 1023;
    int kb = c * 8;

    uint2 fs = g_fsb[b * 32 + lane];
    uint2 ft = g_ftb[b * 32 + lane];

    int rl = (lane < 8) ? cidx[b * K + kb + lane] : 0;

    uint2 w1[8], w2[8];
    #pragma unroll
    for (int j = 0; j < 8; j++) {
        long long ro = (long long)__shfl_sync(FULL, rl, j) * 32 + lane;
        w1[j] = g_b1h[ro];
        w2[j] = g_b2h[ro];
    }
    float d0[8], d1[8];
    #pragma unroll
    for (int j = 0; j < 8; j++) {
        d0[j] = dotbf(w2[j], fs);     // view0: <mv2_row, f_s>
        d1[j] = dotbf(w1[j], ft);     // view1: <mv1_row, f_t>
    }
    #pragma unroll
    for (int off = 16; off > 0; off >>= 1) {
        #pragma unroll
        for (int j = 0; j < 8; j++) {
            d0[j] += __shfl_xor_sync(FULL, d0[j], off);
            d1[j] += __shfl_xor_sync(FULL, d1[j], off);
        }
    }

    // lane j (j<8) takes sums j via compile-time select chain (no spills)
    float my0 = d0[0], my1 = d1[0];
    #pragma unroll
    for (int j = 1; j < 8; j++) {
        if (lane == j) { my0 = d0[j]; my1 = d1[j]; }
    }

    double acc0 = 0.0, acc1 = 0.0;
    if (lane < 8) {
        float e0 = expf(my0 * kINV_T());
        float e1 = expf(my1 * kINV_T());
        g_neg[(size_t)b * K + kb + lane]           = e0;   // view0
        g_neg[(size_t)(B + b) * K + kb + lane]     = e1;   // view1
        acc0 = (double)e0;
        acc1 = (double)e1;
    }
    #pragma unroll
    for (int off = 16; off > 0; off >>= 1) {
        acc0 += __shfl_xor_sync(FULL, acc0, off);
        acc1 += __shfl_xor_sync(FULL, acc1, off);
    }

    __shared__ double shs[16];
    if (lane == 0) { shs[wrp] = acc0; shs[8 + wrp] = acc1; }
    __syncthreads();
    if (threadIdx.x == 0) {
        double s0 = 0.0, s1 = 0.0;
        #pragma unroll
        for (int j = 0; j < 8; j++) { s0 += shs[j]; s1 += shs[8 + j]; }
        atomicAdd(&g_sum[0], s0);
        atomicAdd(&g_sum[1], s1);
    }
}

// --- loss reduction (MLP=4, exact tiling)
__global__ void __launch_bounds__(256) k2_loss() {
    double Z0 = g_sum[0] * (500000.0 / (double)ENT);
    double Z1 = g_sum[1] * (500000.0 / (double)ENT);
    float Zf0 = (float)Z0, Zf1 = (float)Z1;

    const int stride = 512 * 256;                    // 131072 threads
    int tid = blockIdx.x * 256 + threadIdx.x;
    double acc = 0.0;

    #pragma unroll 1
    for (int u = 0; u < 8; u++) {
        int i0 = tid + u * 4 * stride;
        float y0 = g_neg[i0];
        float y1 = g_neg[i0 + stride];
        float y2 = g_neg[i0 + 2 * stride];
        float y3 = g_neg[i0 + 3 * stride];
        float Zf = (i0 < B * K) ? Zf0 : Zf1;         // groups never straddle views
        float t0 = logf(kMPN() / (y0 / Zf + kDENOM()));
        float t1 = logf(kMPN() / (y1 / Zf + kDENOM()));
        float t2 = logf(kMPN() / (y2 / Zf + kDENOM()));
        float t3 = logf(kMPN() / (y3 / Zf + kDENOM()));
        acc += (double)(t0 + t1 + t2 + t3);
    }

    if (blockIdx.x == 0) {
        #pragma unroll
        for (int p = 0; p < 2; p++) {
            int i = threadIdx.x + p * 256;
            float Zf = (i < B) ? Zf0 : Zf1;
            float y = g_pos[i] / Zf;
            acc += (double)logf(y / (y + kDENOM()));
        }
    }

    #pragma unroll
    for (int off = 16; off > 0; off >>= 1)
        acc += __shfl_xor_sync(FULL, acc, off);
    __shared__ double sh[8];
    int lane = threadIdx.x & 31, wid = threadIdx.x >> 5;
    if (lane == 0) sh[wid] = acc;
    __syncthreads();
    if (threadIdx.x == 0) {
        double s = 0.0;
        for (int j = 0; j < 8; j++) s += sh[j];
        atomicAdd(&g_loss, s);
    }
}

// --- momentum scatter update of the 256 touched rows
__global__ void k3_update(const float* __restrict__ f_s, const float* __restrict__ f_t,
                          const float* __restrict__ mv1, const float* __restrict__ mv2,
                          const int* __restrict__ idx, float* __restrict__ out) {
    int u = blockIdx.x;       // 512 blocks
    int v = u >> 8;
    int b = u & 255;
    if (!g_winner[b]) return;
    int row = idx[b];
    const float* mem = v ? mv2 : mv1;
    const float* f   = v ? f_t : f_s;
    float* dst = out + 1 + (size_t)v * BANK + (size_t)row * D;
    int t = threadIdx.x;      // 128 threads
    float nv = mem[(long long)row * D + t] * 0.5f + f[b * D + t] * 0.5f;
    float s = nv * nv;
    #pragma unroll
    for (int off = 16; off > 0; off >>= 1)
        s += __shfl_xor_sync(FULL, s, off);
    __shared__ float sh[4];
    if ((t & 31) == 0) sh[t >> 5] = s;
    __syncthreads();
    float tot = sh[0] + sh[1] + sh[2] + sh[3];
    dst[t] = nv / sqrtf(tot);
}

__global__ void k_final(float* __restrict__ out) {
    out[0] = (float)(-g_loss / 256.0);
}

extern "C" void kernel_launch(void* const* d_in, const int* in_sizes, int n_in,
                              void* d_out, int out_size) {
    const float* f_s  = (const float*)d_in[0];
    const float* f_t  = (const float*)d_in[1];
    const float* mv1  = (const float*)d_in[2];
    const float* mv2  = (const float*)d_in[3];
    const int*   idx  = (const int*)d_in[4];
    const int*   cidx = (const int*)d_in[5];
    float* out = (float*)d_out;

    k_zero<<<16, 256>>>(idx, f_s, f_t, mv1, mv2, out);
    k_stream<<<16384, 256>>>(mv1, mv2, out);
    k_gather<<<32832, 256>>>(f_s, f_t, mv1, mv2, idx, cidx);
    k2_loss<<<512, 256>>>();
    k3_update<<<512, 128>>>(f_s, f_t, mv1, mv2, idx, out);
    k_final<<<1, 1>>>(out);
}